// round 4
// baseline (speedup 1.0000x reference)
#include <cuda_runtime.h>
#include <math.h>

// MFHawkes factorized O(B*L*D), single kernel, per-batch flag-based sync.
//   t = times/1e4, ab = |beta|
//   w_j = exp(ab*t_j)*mask_j ;  g_j = 1 - exp(-ab*(t_last - t_j))
//   P_i = sum_{j<i} w_j e_j (exclusive prefix) ; v = sum_j g_j e_j
//   S1_i = ab*exp(-ab*t_i)*(e_i.P_i) ; lam = |S1+u_i|+1e-6
//   out[b] = sum_i ( -log(lam_i) + u_i*horizon + e_i.v )

#define HK_L     2048
#define HK_D     64
#define HK_B     4
#define HK_CHUNK 8                      // events per warp
#define HK_WPB   16                     // warps per block (512 threads)
#define HK_EPB   (HK_WPB * HK_CHUNK)    // 128 events per block
#define HK_BPB   (HK_L / HK_EPB)        // 16 blocks per batch
#define HK_NBLK  (HK_B * HK_BPB)        // 64 blocks

__device__ float    g_T[HK_NBLK * HK_D];     // per-block totals of w*e
__device__ float    g_V[HK_NBLK * HK_D];     // per-block totals of g*e
__device__ double   g_part[HK_NBLK];         // per-block result partials
__device__ unsigned g_f1[HK_NBLK];           // publish flags (totals)
__device__ unsigned g_f2[HK_NBLK];           // publish flags (partials)

__global__ __launch_bounds__(HK_WPB * 32, 1)
void mfhawkes_fused(const int*   __restrict__ ids,
                    const float* __restrict__ times,
                    const float* __restrict__ mask,
                    const float* __restrict__ emb,
                    const float* __restrict__ u_table,
                    const float* __restrict__ beta,
                    float*       __restrict__ out)
{
    __shared__ float  Tsm[HK_WPB][HK_D];
    __shared__ float  Vsm[HK_WPB][HK_D];
    __shared__ float  basesm[HK_D];
    __shared__ float  vsm[HK_D];
    __shared__ double racc[HK_WPB];

    const int tid    = threadIdx.x;
    const int warp   = tid >> 5;
    const int lane   = tid & 31;
    const int blk    = blockIdx.x;
    const int batch  = blk / HK_BPB;
    const int blk_in = blk % HK_BPB;

    // generation: all flags equal between launches; this launch targets gen
    const unsigned gen = g_f1[blk] + 1u;

    const float ab      = fabsf(beta[0]);
    const float tlast   = times[batch * HK_L + HK_L - 1] * (1.0f / 10000.0f);
    const float horizon = tlast - times[batch * HK_L + 1] * (1.0f / 10000.0f);

    // ---- Phase A: gather into registers, per-warp chunk totals
    const int i0 = batch * HK_L + blk_in * HK_EPB + warp * HK_CHUNK;

    float e0[HK_CHUNK], e1[HK_CHUNK], w[HK_CHUNK], u[HK_CHUNK], kx[HK_CHUNK];
    float T0 = 0.f, T1 = 0.f, V0 = 0.f, V1 = 0.f;
    #pragma unroll
    for (int i = 0; i < HK_CHUNK; i++) {
        const int   id = ids[i0 + i];
        const float ti = times[i0 + i] * (1.0f / 10000.0f);
        const float wm = mask[i0 + i];
        e0[i] = emb[id * HK_D + lane];
        e1[i] = emb[id * HK_D + lane + 32];
        u[i]  = fabsf(u_table[id]);
        w[i]  = __expf(ab * ti) * wm;
        kx[i] = ab * __expf(-ab * ti);
        const float g = 1.0f - __expf(ab * (ti - tlast));
        T0 += w[i] * e0[i];  T1 += w[i] * e1[i];
        V0 += g    * e0[i];  V1 += g    * e1[i];
    }
    Tsm[warp][lane]      = T0;  Tsm[warp][lane + 32] = T1;
    Vsm[warp][lane]      = V0;  Vsm[warp][lane + 32] = V1;
    __syncthreads();

    // ---- intra-block exclusive scan over warps, publish block totals
    if (tid < HK_D) {
        const int d = tid;
        float run = 0.f, vv = 0.f;
        #pragma unroll
        for (int c = 0; c < HK_WPB; c++) {
            const float tt = Tsm[c][d];
            Tsm[c][d] = run;                // warp-exclusive base within block
            run += tt;
            vv  += Vsm[c][d];
        }
        g_T[blk * HK_D + d] = run;
        g_V[blk * HK_D + d] = vv;
        __threadfence();                    // make totals visible before flag
    }
    __syncthreads();
    if (tid == 0)
        ((volatile unsigned*)g_f1)[blk] = gen;

    // ---- wait for the 15 peers in this batch
    if (tid < HK_BPB - 1) {
        const int peer = batch * HK_BPB + tid + (tid >= blk_in ? 1 : 0);
        while (((volatile unsigned*)g_f1)[peer] < gen) { }
        __threadfence();
    }
    __syncthreads();

    // ---- cross-block exclusive base + v reduction
    if (tid < HK_D) {
        const int d = tid;
        float base = 0.f, vv = 0.f;
        #pragma unroll
        for (int k = 0; k < HK_BPB; k++) {
            const float tb = g_T[(batch * HK_BPB + k) * HK_D + d];
            const float tv = g_V[(batch * HK_BPB + k) * HK_D + d];
            if (k < blk_in) base += tb;
            vv += tv;
        }
        basesm[d] = base;
        vsm[d]    = vv;
    }
    __syncthreads();

    // ---- Phase C: 8-step serial scan per warp (embeddings in registers)
    {
        float P0 = basesm[lane]      + Tsm[warp][lane];
        float P1 = basesm[lane + 32] + Tsm[warp][lane + 32];
        const float v0 = vsm[lane], v1 = vsm[lane + 32];
        double acc = 0.0;
        #pragma unroll
        for (int i = 0; i < HK_CHUNK; i++) {
            float d1 = e0[i] * P0 + e1[i] * P1;
            float d2 = e0[i] * v0 + e1[i] * v1;
            #pragma unroll
            for (int off = 16; off; off >>= 1) {
                d1 += __shfl_xor_sync(0xffffffffu, d1, off);
                d2 += __shfl_xor_sync(0xffffffffu, d2, off);
            }
            const float lam = fabsf(kx[i] * d1 + u[i]) + 1e-6f;
            acc += (double)(-__logf(lam) + u[i] * horizon + d2);
            P0 += w[i] * e0[i];
            P1 += w[i] * e1[i];
        }
        if (lane == 0) racc[warp] = acc;
    }
    __syncthreads();

    // ---- block partial, publish
    if (warp == 0) {
        double a = (lane < HK_WPB) ? racc[lane] : 0.0;
        #pragma unroll
        for (int off = 8; off; off >>= 1)
            a += __shfl_xor_sync(0xffffffffu, a, off);
        if (lane == 0) {
            g_part[blk] = a;
            __threadfence();
            ((volatile unsigned*)g_f2)[blk] = gen;
        }
    }

    // ---- leader block sums batch partials
    if (blk_in == 0) {
        if (tid >= 1 && tid < HK_BPB) {
            while (((volatile unsigned*)g_f2)[batch * HK_BPB + tid] < gen) { }
            __threadfence();
        }
        __syncthreads();
        if (tid == 0) {
            double s = 0.0;
            #pragma unroll
            for (int k = 0; k < HK_BPB; k++)
                s += g_part[batch * HK_BPB + k];
            out[batch] = (float)s;
        }
    }
}

extern "C" void kernel_launch(void* const* d_in, const int* in_sizes, int n_in,
                              void* d_out, int out_size)
{
    const int*   ids     = (const int*)  d_in[0];
    const float* times   = (const float*)d_in[1];
    const float* mask    = (const float*)d_in[2];
    const float* emb     = (const float*)d_in[3];
    const float* u_table = (const float*)d_in[4];
    const float* beta    = (const float*)d_in[5];
    float*       out     = (float*)d_out;

    mfhawkes_fused<<<HK_NBLK, HK_WPB * 32>>>(ids, times, mask, emb, u_table, beta, out);
}

// round 5
// speedup vs baseline: 1.3851x; 1.3851x over previous
#include <cuda_runtime.h>
#include <math.h>

// MFHawkes factorized O(B*L*D), single kernel, per-batch atomic barriers.
//   t = times/1e4, ab = |beta|
//   w_j = exp(ab*t_j)*mask_j ;  g_j = 1 - exp(-ab*(t_last - t_j))
//   P_i = sum_{j<i} w_j e_j (exclusive prefix) ; v = sum_j g_j e_j ; E = sum_i e_i
//   lam_i = |ab*exp(-ab*t_i)*(e_i.P_i) + u_i| + 1e-6
//   out[b] = sum_i ( -log(lam_i) + u_i*horizon ) + E.v

#define HK_L     2048
#define HK_D     64
#define HK_B     4
#define HK_CHUNK 8                      // events per warp
#define HK_WPB   8                      // warps per block (256 threads)
#define HK_EPB   (HK_WPB * HK_CHUNK)    // 64 events per block
#define HK_BPB   (HK_L / HK_EPB)        // 32 blocks per batch
#define HK_NBLK  (HK_B * HK_BPB)        // 128 blocks

__device__ float    g_T[HK_NBLK * HK_D];     // per-block totals of w*e
__device__ float    g_V[HK_NBLK * HK_D];     // per-block totals of g*e
__device__ float    g_E[HK_NBLK * HK_D];     // per-block totals of e
__device__ unsigned g_cnt[HK_B * 32];        // per-batch arrive counters (line-separated)
__device__ volatile unsigned g_flg[HK_B * 32];

__device__ __forceinline__ void batch_sync(int batch)
{
    __syncthreads();
    if (threadIdx.x == 0) {
        const int idx = batch * 32;
        const unsigned old = g_flg[idx];
        __threadfence();
        const unsigned n = atomicAdd(&g_cnt[idx], 1u);
        if (n == HK_BPB - 1) {
            g_cnt[idx] = 0;              // self-reset for next replay
            __threadfence();
            g_flg[idx] = old + 1;        // release
        } else {
            while (g_flg[idx] == old) { }
            __threadfence();
        }
    }
    __syncthreads();
}

__global__ __launch_bounds__(HK_WPB * 32, 1)
void mfhawkes_fused(const int*   __restrict__ ids,
                    const float* __restrict__ times,
                    const float* __restrict__ mask,
                    const float* __restrict__ emb,
                    const float* __restrict__ u_table,
                    const float* __restrict__ beta,
                    float*       __restrict__ out)
{
    __shared__ float  Tsm[HK_WPB][HK_D];
    __shared__ float  Vsm[HK_WPB][HK_D];
    __shared__ float  Esm[HK_WPB][HK_D];
    __shared__ float  basesm[HK_D];
    __shared__ float  prodsm[HK_D];      // E_d * v_d (leader block only)
    __shared__ double racc[HK_WPB];

    const int tid    = threadIdx.x;
    const int warp   = tid >> 5;
    const int lane   = tid & 31;
    const int batch  = blockIdx.x / HK_BPB;
    const int blk_in = blockIdx.x % HK_BPB;

    const float ab      = fabsf(beta[0]);
    const float tlast   = times[batch * HK_L + HK_L - 1] * (1.0f / 10000.0f);
    const float horizon = tlast - times[batch * HK_L + 1] * (1.0f / 10000.0f);

    if (blk_in == 0 && tid == 0) out[batch] = 0.0f;

    // ---- Phase A: gather into registers, per-warp chunk totals
    const int i0 = batch * HK_L + blk_in * HK_EPB + warp * HK_CHUNK;

    float e0[HK_CHUNK], e1[HK_CHUNK], w[HK_CHUNK], u[HK_CHUNK], kx[HK_CHUNK];
    float T0 = 0.f, T1 = 0.f, V0 = 0.f, V1 = 0.f, E0 = 0.f, E1 = 0.f;
    #pragma unroll
    for (int i = 0; i < HK_CHUNK; i++) {
        const int   id = ids[i0 + i];
        const float ti = times[i0 + i] * (1.0f / 10000.0f);
        const float wm = mask[i0 + i];
        e0[i] = emb[id * HK_D + lane];
        e1[i] = emb[id * HK_D + lane + 32];
        u[i]  = fabsf(u_table[id]);
        w[i]  = __expf(ab * ti) * wm;
        kx[i] = ab * __expf(-ab * ti);
        const float g = 1.0f - __expf(ab * (ti - tlast));
        T0 += w[i] * e0[i];  T1 += w[i] * e1[i];
        V0 += g    * e0[i];  V1 += g    * e1[i];
        E0 += e0[i];         E1 += e1[i];
    }
    Tsm[warp][lane] = T0;  Tsm[warp][lane + 32] = T1;
    Vsm[warp][lane] = V0;  Vsm[warp][lane + 32] = V1;
    Esm[warp][lane] = E0;  Esm[warp][lane + 32] = E1;
    __syncthreads();

    // ---- intra-block exclusive scan over warps, publish block totals
    if (tid < HK_D) {
        const int d = tid;
        float run = 0.f, vv = 0.f, ee = 0.f;
        #pragma unroll
        for (int c = 0; c < HK_WPB; c++) {
            const float tt = Tsm[c][d];
            Tsm[c][d] = run;                 // warp-exclusive base within block
            run += tt;
            vv  += Vsm[c][d];
            ee  += Esm[c][d];
        }
        g_T[blockIdx.x * HK_D + d] = run;
        g_V[blockIdx.x * HK_D + d] = vv;
        g_E[blockIdx.x * HK_D + d] = ee;
    }
    __threadfence();

    batch_sync(batch);

    // ---- cross-block exclusive base; leader also computes E.v
    if (tid < HK_D) {
        const int d = tid;
        float base = 0.f;
        #pragma unroll
        for (int k = 0; k < HK_BPB; k++) {
            const float tb = g_T[(batch * HK_BPB + k) * HK_D + d];
            if (k < blk_in) base += tb;
        }
        basesm[d] = base;
        if (blk_in == 0) {
            float vv = 0.f, ee = 0.f;
            #pragma unroll
            for (int k = 0; k < HK_BPB; k++) {
                vv += g_V[(batch * HK_BPB + k) * HK_D + d];
                ee += g_E[(batch * HK_BPB + k) * HK_D + d];
            }
            prodsm[d] = vv * ee;
        }
    }
    __syncthreads();

    // ---- Phase C: serial P chain (pure FFMA), then batched d1 reduction
    {
        float P0 = basesm[lane]      + Tsm[warp][lane];
        float P1 = basesm[lane + 32] + Tsm[warp][lane + 32];
        float d1[HK_CHUNK];
        #pragma unroll
        for (int i = 0; i < HK_CHUNK; i++) {
            d1[i] = e0[i] * P0 + e1[i] * P1;
            P0 += w[i] * e0[i];
            P1 += w[i] * e1[i];
        }
        // 8 interleaved butterfly reductions (pipelined shfl chains)
        #pragma unroll
        for (int off = 16; off; off >>= 1) {
            #pragma unroll
            for (int i = 0; i < HK_CHUNK; i++)
                d1[i] += __shfl_xor_sync(0xffffffffu, d1[i], off);
        }
        // all lanes now hold all 8 full sums; uniform tail
        double acc = 0.0;
        #pragma unroll
        for (int i = 0; i < HK_CHUNK; i++) {
            const float lam = fabsf(kx[i] * d1[i] + u[i]) + 1e-6f;
            acc += (double)(-__logf(lam) + u[i] * horizon);
        }
        if (lane == 0) racc[warp] = acc;
    }
    __syncthreads();

    // ---- block partial -> atomicAdd; leader adds E.v
    if (warp == 0) {
        double a = (lane < HK_WPB) ? racc[lane] : 0.0;
        #pragma unroll
        for (int off = 4; off; off >>= 1)
            a += __shfl_xor_sync(0xffffffffu, a, off);
        float extra = 0.f;
        if (blk_in == 0) {
            float p = prodsm[lane] + prodsm[lane + 32];
            #pragma unroll
            for (int off = 16; off; off >>= 1)
                p += __shfl_xor_sync(0xffffffffu, p, off);
            extra = p;
        }
        if (lane == 0) atomicAdd(&out[batch], (float)a + extra);
    }
}

extern "C" void kernel_launch(void* const* d_in, const int* in_sizes, int n_in,
                              void* d_out, int out_size)
{
    const int*   ids     = (const int*)  d_in[0];
    const float* times   = (const float*)d_in[1];
    const float* mask    = (const float*)d_in[2];
    const float* emb     = (const float*)d_in[3];
    const float* u_table = (const float*)d_in[4];
    const float* beta    = (const float*)d_in[5];
    float*       out     = (float*)d_out;

    mfhawkes_fused<<<HK_NBLK, HK_WPB * 32>>>(ids, times, mask, emb, u_table, beta, out);
}